// round 4
// baseline (speedup 1.0000x reference)
#include <cuda_runtime.h>
#include <cuda_bf16.h>
#include <math.h>

// Problem constants (fixed-shape problem)
#define MAXN 50000
#define MAXE 800000
#define FDIM 128
#define CDIM 8

// ---------------- scratch (static __device__, no allocation) ----------------
__device__ int   d_is64;             // edge_index dtype flag (runtime-detected)
__device__ int   d_row[MAXE];        // canonical int32 source nodes
__device__ int   d_col[MAXE];        // canonical int32 target nodes
__device__ int   d_cnt[MAXN];        // edge count per target node (no self loop)
__device__ int   d_offs[MAXN + 1];   // CSR offsets
__device__ int   d_cursor[MAXN];     // scatter cursors
__device__ float d_dinv[MAXN];       // 1/sqrt(deg) incl. self loop
__device__ int   d_csr[MAXE];        // source node per edge, sorted by target
__device__ float d_bufA[(size_t)MAXN * FDIM];  // ping
__device__ float d_bufB[(size_t)MAXN * FDIM];  // pong

// ---------------- edge dtype detection + canonicalization ----------------
// If edge_index is int64 (little-endian), every odd 32-bit word is a high half
// of a value < 50000 -> 0. If int32, odd words are random node ids.
__global__ void detect_kernel(const unsigned int* __restrict__ w) {
    if (threadIdx.x == 0 && blockIdx.x == 0) {
        unsigned int acc = 0;
        #pragma unroll
        for (int i = 0; i < 64; i++) acc |= w[2 * i + 1];
        d_is64 = (acc == 0) ? 1 : 0;
    }
}

__global__ void convert_kernel(const int* __restrict__ w, int e) {
    int i = blockIdx.x * blockDim.x + threadIdx.x;
    if (i >= e) return;
    if (d_is64) {
        d_row[i] = w[2 * i];            // low word of row[i]
        d_col[i] = w[2 * (e + i)];      // low word of col[i]
    } else {
        d_row[i] = w[i];
        d_col[i] = w[e + i];
    }
}

// ---------------- CSR construction ----------------
__global__ void zero_cnt_kernel(int n) {
    int i = blockIdx.x * blockDim.x + threadIdx.x;
    if (i < n) d_cnt[i] = 0;
}

__global__ void hist_kernel(int e) {
    int i = blockIdx.x * blockDim.x + threadIdx.x;
    if (i < e) atomicAdd(&d_cnt[d_col[i]], 1);
}

// single-block exclusive scan of d_cnt -> d_offs (n up to 50000)
__global__ void scan_kernel(int n) {
    __shared__ int warp_sums[32];
    __shared__ int s_carry;
    const int tid = threadIdx.x;
    const int lane = tid & 31, wid = tid >> 5;
    if (tid == 0) { d_offs[0] = 0; s_carry = 0; }
    __syncthreads();
    for (int base = 0; base < n; base += 1024) {
        int i = base + tid;
        int v = (i < n) ? d_cnt[i] : 0;
        int x = v;
        #pragma unroll
        for (int o = 1; o < 32; o <<= 1) {
            int t = __shfl_up_sync(0xffffffffu, x, o);
            if (lane >= o) x += t;
        }
        if (lane == 31) warp_sums[wid] = x;
        __syncthreads();
        if (wid == 0) {
            int s = warp_sums[lane];
            #pragma unroll
            for (int o = 1; o < 32; o <<= 1) {
                int t = __shfl_up_sync(0xffffffffu, s, o);
                if (lane >= o) s += t;
            }
            warp_sums[lane] = s;
        }
        __syncthreads();
        int prefix = s_carry + (wid > 0 ? warp_sums[wid - 1] : 0) + x;
        if (i < n) d_offs[i + 1] = prefix;
        __syncthreads();
        if (tid == 0) s_carry += warp_sums[31];
        __syncthreads();
    }
}

__global__ void prep_kernel(int n) {
    int i = blockIdx.x * blockDim.x + threadIdx.x;
    if (i < n) {
        d_dinv[i] = rsqrtf((float)(d_cnt[i] + 1));  // +1 self loop; deg >= 1 always
        d_cursor[i] = d_offs[i];
    }
}

__global__ void scatter_kernel(int e) {
    int i = blockIdx.x * blockDim.x + threadIdx.x;
    if (i < e) {
        int c = d_col[i];
        int p = atomicAdd(&d_cursor[c], 1);
        d_csr[p] = d_row[i];
    }
}

// ---------------- GEMM: out[r][:] = dinv[r] * (A[r][:] @ W)  (128x128 W) ----------------
// block: 256 threads, tile 64 rows x 128 cols, full K=128.
// dynamic smem: As[64*128] + Ws[128*128] = 96 KB
__global__ void __launch_bounds__(256) gemm_scaled_kernel(
    const float* __restrict__ A, const float* __restrict__ W,
    float* __restrict__ out, int n)
{
    extern __shared__ float sh[];
    float* As = sh;               // 64*128
    float* Ws = sh + 64 * 128;    // 128*128
    const int tid = threadIdx.x;
    const int row0 = blockIdx.x * 64;

    // load W (16384 floats = 4096 float4, 16 per thread)
    {
        const float4* Wv = (const float4*)W;
        float4* Wsv = (float4*)Ws;
        #pragma unroll
        for (int i = 0; i < 16; i++) Wsv[tid + i * 256] = Wv[tid + i * 256];
    }
    // load A tile (8192 floats = 2048 float4, 8 per thread)
    {
        float4* Asv = (float4*)As;
        #pragma unroll
        for (int i = 0; i < 8; i++) {
            int idx = tid + i * 256;            // float4 index within tile
            int r = row0 + (idx >> 5);
            float4 v = make_float4(0.f, 0.f, 0.f, 0.f);
            if (r < n) v = ((const float4*)A)[(size_t)r * 32 + (idx & 31)];
            Asv[idx] = v;
        }
    }
    __syncthreads();

    const int tc = tid & 31;   // 32 col-groups of 4
    const int tr = tid >> 5;   // 8 row-groups of 8
    float acc[8][4];
    #pragma unroll
    for (int i = 0; i < 8; i++)
        #pragma unroll
        for (int j = 0; j < 4; j++) acc[i][j] = 0.f;

    const float* AsBase = As + (tr * 8) * 128;
    const float* WsBase = Ws + tc * 4;
    #pragma unroll 4
    for (int k = 0; k < 128; k++) {
        float4 b = *(const float4*)(WsBase + k * 128);
        #pragma unroll
        for (int i = 0; i < 8; i++) {
            float a = AsBase[i * 128 + k];
            acc[i][0] += a * b.x;
            acc[i][1] += a * b.y;
            acc[i][2] += a * b.z;
            acc[i][3] += a * b.w;
        }
    }

    #pragma unroll
    for (int i = 0; i < 8; i++) {
        int r = row0 + tr * 8 + i;
        if (r < n) {
            float s = d_dinv[r];
            float4 v = make_float4(acc[i][0] * s, acc[i][1] * s, acc[i][2] * s, acc[i][3] * s);
            *(float4*)(out + (size_t)r * 128 + tc * 4) = v;
        }
    }
}

// ---------------- Aggregation: warp per node ----------------
// out[c][:] = dinv[c] * ( g[c][:] + sum_{edges r->c} g[r][:] ) + bias[:]
__global__ void agg_kernel(const float* __restrict__ g, const float* __restrict__ bias,
                           float* __restrict__ outh, int n)
{
    const int warp = (blockIdx.x * blockDim.x + threadIdx.x) >> 5;
    const int lane = threadIdx.x & 31;
    if (warp >= n) return;
    const int node = warp;

    float4 acc = *(const float4*)(g + (size_t)node * 128 + lane * 4);  // self loop
    const int s = d_offs[node], e = d_offs[node + 1];
    for (int i = s; i < e; i += 32) {
        int idx = (i + lane < e) ? d_csr[i + lane] : 0;
        int cnt = min(32, e - i);
        for (int j = 0; j < cnt; j++) {
            int r = __shfl_sync(0xffffffffu, idx, j);
            float4 v = *(const float4*)(g + (size_t)r * 128 + lane * 4);
            acc.x += v.x; acc.y += v.y; acc.z += v.z; acc.w += v.w;
        }
    }
    const float dv = d_dinv[node];
    float4 b = *(const float4*)(bias + lane * 4);
    float4 o = make_float4(acc.x * dv + b.x, acc.y * dv + b.y,
                           acc.z * dv + b.z, acc.w * dv + b.w);
    *(float4*)(outh + (size_t)node * 128 + lane * 4) = o;
}

// ---------------- Aggregation 2 fused with final FC (128 -> 8) ----------------
__global__ void agg_fc_kernel(const float* __restrict__ g, const float* __restrict__ b2,
                              const float* __restrict__ Wfc, const float* __restrict__ bfc,
                              float* __restrict__ out, int n)
{
    __shared__ float sWt[CDIM * 128];   // transposed: sWt[j*128 + f]
    __shared__ float sb[CDIM];
    const int tid = threadIdx.x;
    for (int i = tid; i < CDIM * 128; i += blockDim.x) {
        int f = i >> 3, j = i & 7;      // i = f*8 + j in source layout
        sWt[j * 128 + f] = Wfc[i];
    }
    if (tid < CDIM) sb[tid] = bfc[tid];
    __syncthreads();

    const int warp = (blockIdx.x * blockDim.x + tid) >> 5;
    const int lane = tid & 31;
    if (warp >= n) return;
    const int node = warp;

    float4 acc = *(const float4*)(g + (size_t)node * 128 + lane * 4);
    const int s = d_offs[node], e = d_offs[node + 1];
    for (int i = s; i < e; i += 32) {
        int idx = (i + lane < e) ? d_csr[i + lane] : 0;
        int cnt = min(32, e - i);
        for (int j = 0; j < cnt; j++) {
            int r = __shfl_sync(0xffffffffu, idx, j);
            float4 v = *(const float4*)(g + (size_t)r * 128 + lane * 4);
            acc.x += v.x; acc.y += v.y; acc.z += v.z; acc.w += v.w;
        }
    }
    const float dv = d_dinv[node];
    float4 bb = *(const float4*)(b2 + lane * 4);
    float h0 = acc.x * dv + bb.x;
    float h1 = acc.y * dv + bb.y;
    float h2 = acc.z * dv + bb.z;
    float h3 = acc.w * dv + bb.w;

    float p[CDIM];
    #pragma unroll
    for (int j = 0; j < CDIM; j++) {
        float4 w = *(const float4*)(sWt + j * 128 + lane * 4);  // conflict-free LDS.128
        p[j] = h0 * w.x + h1 * w.y + h2 * w.z + h3 * w.w;
    }
    #pragma unroll
    for (int o = 16; o >= 1; o >>= 1)
        #pragma unroll
        for (int j = 0; j < CDIM; j++)
            p[j] += __shfl_xor_sync(0xffffffffu, p[j], o);

    if (lane == 0) {
        float4 o0 = make_float4(p[0] + sb[0], p[1] + sb[1], p[2] + sb[2], p[3] + sb[3]);
        float4 o1 = make_float4(p[4] + sb[4], p[5] + sb[5], p[6] + sb[6], p[7] + sb[7]);
        *(float4*)(out + (size_t)node * CDIM) = o0;
        *(float4*)(out + (size_t)node * CDIM + 4) = o1;
    }
}

// ---------------- launch ----------------
extern "C" void kernel_launch(void* const* d_in, const int* in_sizes, int n_in,
                              void* d_out, int out_size)
{
    const float* x   = (const float*)d_in[0];
    const int*   ei  = (const int*)  d_in[1];   // int32 OR int64 edge_index [2, E] (runtime-detected)
    const float* W1  = (const float*)d_in[2];
    const float* b1  = (const float*)d_in[3];
    const float* W2  = (const float*)d_in[4];
    const float* b2  = (const float*)d_in[5];
    const float* Wfc = (const float*)d_in[6];
    const float* bfc = (const float*)d_in[7];
    float* out = (float*)d_out;

    const int N = in_sizes[0] / FDIM;
    const int E = in_sizes[1] / 2;   // element count is 2E for either dtype

    // opt-in smem for the GEMM kernel (96 KB dynamic); idempotent, capture-safe
    static const size_t GEMM_SMEM = (64 * 128 + 128 * 128) * sizeof(float);
    cudaFuncSetAttribute(gemm_scaled_kernel,
                         cudaFuncAttributeMaxDynamicSharedMemorySize, (int)GEMM_SMEM);

    float* bufA;  cudaGetSymbolAddress((void**)&bufA, d_bufA);
    float* bufB;  cudaGetSymbolAddress((void**)&bufB, d_bufB);

    const int nb_N = (N + 255) / 256;
    const int nb_E = (E + 255) / 256;
    const int nb_W = (N + 7) / 8;          // warp per node, 8 warps/block
    const int nb_G = (N + 63) / 64;

    // edge dtype canonicalization + CSR build + norm
    detect_kernel<<<1, 32>>>((const unsigned int*)ei);
    convert_kernel<<<nb_E, 256>>>(ei, E);
    zero_cnt_kernel<<<nb_N, 256>>>(N);
    hist_kernel<<<nb_E, 256>>>(E);
    scan_kernel<<<1, 1024>>>(N);
    prep_kernel<<<nb_N, 256>>>(N);
    scatter_kernel<<<nb_E, 256>>>(E);

    // layer 1: g1 = dinv .* (X @ W1) ; h1 = dinv .* (A_sum g1) + b1
    gemm_scaled_kernel<<<nb_G, 256, GEMM_SMEM>>>(x, W1, bufA, N);
    agg_kernel<<<nb_W, 256>>>(bufA, b1, bufB, N);

    // layer 2: g2 = dinv .* (h1 @ W2) ; out = FC(dinv .* (A_sum g2) + b2)
    gemm_scaled_kernel<<<nb_G, 256, GEMM_SMEM>>>(bufB, W2, bufA, N);
    agg_fc_kernel<<<nb_W, 256>>>(bufA, b2, Wfc, bfc, out, N);
}